// round 10
// baseline (speedup 1.0000x reference)
#include <cuda_runtime.h>
#include <cstdint>

// MPS memory encoder, Round 7: two independent barrier domains per CTA.
//   x:     [B=2048, N=128, F=64]      f32
//   cores: [N=128, D=32, F=64, D=32]  f32
//   out[B,256] = (chain(res0=start; res <- res @ (x_i . core_i)) @ end) @ fc_w^T + fc_b
//
// Geometry: grid=128 CTAs x 512 threads, NB=16 batches/CTA.
//   Half h = tid>>8 owns f-range [32h, 32h+32), with its OWN triple-buffered
//   cp.async stream (16KB chunks = 4 f-slices) and its OWN named barrier
//   (bar.sync 1+h, 256). Halves converge only at the per-site reduction.
//   Within a half: thread = 4 batches x 4 r x 4 d (bpl=tid&3, rq=(tid>>2)&7,
//   dq=(tid>>5)&7) -> LDS.128 with 4-way batch broadcast, conflict-free.

#define NSITES   128
#define FEAT     64
#define DB       32
#define OUTD     256
#define NB       16
#define THREADS  512
#define HALFT    256
#define CPS      8                        // chunks per site per half (4 f each)
#define NCHUNK_H (NSITES * CPS)           // 1024 per half
#define CHUNK_B  16384                    // 4 f-slices * 32 d * 32 r * 4B
#define SITE_FLOATS (DB * FEAT * DB)      // 131072

// smem byte offsets
#define BUF_OFF   0                       // [2 halves][3 bufs][16KB] = 96KB
#define X_OFF     98304                   // [2][16][65] u64 (x duplicated pairs)
#define RES_OFF   114944                  // [16][33] floats
#define PART_OFF  117056                  // [16][16][36] floats
#define VAL_OFF   153920                  // [16] floats
#define SMEM_TOTAL 153984

typedef unsigned long long u64;

__device__ __forceinline__ u64 pack2(float a, float b) {
    u64 r;
    asm("mov.b64 %0, {%1, %2};" : "=l"(r)
        : "r"(__float_as_uint(a)), "r"(__float_as_uint(b)));
    return r;
}

__device__ __forceinline__ u64 fma2(u64 a, u64 b, u64 c) {
    u64 d;
    asm("fma.rn.f32x2 %0, %1, %2, %3;" : "=l"(d) : "l"(a), "l"(b), "l"(c));
    return d;
}

__device__ __forceinline__ void cp16(uint32_t dst, const float* src) {
    asm volatile("cp.async.cg.shared.global [%0], [%1], 16;\n"
                 :: "r"(dst), "l"(src));
}

__device__ __forceinline__ void half_bar(int h) {
    asm volatile("bar.sync %0, %1;" :: "r"(1 + h), "r"(HALFT) : "memory");
}

// Stage chunk gh (per-half id) of this half's f-range into buffer gh%3.
//   chunk c of site s covers global f in [h*32 + c*4, +4).
//   gmem float idx = s*131072 + d*2048 + f*32 + r
//   buffer float idx = d*128 + fl*32 + r   (fl = f - chunk base)
__device__ __forceinline__ void issue_chunk(int gh, int h, int lid,
                                            uint32_t smem_base,
                                            const float* __restrict__ cores) {
    if (gh < NCHUNK_H) {
        int s = gh >> 3, c = gh & 7;
        const float* base = cores + (size_t)s * SITE_FLOATS + h * 1024 + c * 128;
        uint32_t dst = smem_base
                     + (uint32_t)((h * 3 + (gh % 3)) * CHUNK_B) + lid * 16;
        #pragma unroll
        for (int k = 0; k < 4; ++k) {
            int u = lid + k * HALFT;          // 16B unit id, 1024 per chunk
            int d = u >> 5, w = u & 31;
            cp16(dst + k * 4096, base + d * 2048 + w * 4);
        }
    }
    asm volatile("cp.async.commit_group;\n");   // uniform group counting
}

__global__ __launch_bounds__(THREADS, 1)
void mps_encoder_kernel(const float* __restrict__ x,
                        const float* __restrict__ cores,
                        const float* __restrict__ start,
                        const float* __restrict__ endv,
                        const float* __restrict__ fc_w,
                        const float* __restrict__ fc_b,
                        float* __restrict__ out)
{
    extern __shared__ char smem[];
    float* buff  = (float*)(smem + BUF_OFF);
    u64*   x2    = (u64*)  (smem + X_OFF);     // [2][16][65]
    float* res_s = (float*)(smem + RES_OFF);   // [16][33]
    float* part  = (float*)(smem + PART_OFF);  // [16][16][36]
    float* val_s = (float*)(smem + VAL_OFF);

    const uint32_t smem_base = (uint32_t)__cvta_generic_to_shared(smem);

    const int tid = threadIdx.x;
    const int h   = tid >> 8;            // half: f-range [32h, 32h+32)
    const int lid = tid & 255;
    const int bpl = tid & 3;
    const int rq  = (tid >> 2) & 7;
    const int dq  = (tid >> 5) & 7;
    const int r0  = 4 * rq;
    const int d0  = 4 * dq;
    const int B0  = 4 * bpl;
    const int slice = h * 8 + dq;        // reduction slice id (0..15)
    const int bbase = blockIdx.x * NB;

    // init res = start (512 slots, 1 per thread)
    {
        int b = tid >> 5, d = tid & 31;
        res_s[b * 33 + d] = start[d];
    }

    const float4* x4 = reinterpret_cast<const float4*>(x);

    // stage x for site 0 (threads 0..255, duplicated (x,x) pairs)
    if (tid < NB * 16) {
        int br = tid >> 4, q = tid & 15;
        float4 xv = x4[((size_t)(bbase + br) * NSITES + 0) * 16 + q];
        u64* dstx = &x2[(size_t)br * 65 + 4 * q];
        dstx[0] = pack2(xv.x, xv.x); dstx[1] = pack2(xv.y, xv.y);
        dstx[2] = pack2(xv.z, xv.z); dstx[3] = pack2(xv.w, xv.w);
    }

    // prologue: each half prefetches its chunks 0 and 1
    issue_chunk(0, h, lid, smem_base, cores);
    issue_chunk(1, h, lid, smem_base, cores);

    __syncthreads();   // x(site0) + res_s visible to all

    u64 rp[4][4];      // rp[bb][i] = (res[B0+bb][d0+i], dup)
    const u64 zero = 0;

    for (int site = 0; site < NSITES; ++site) {
        u64 acc[4][2];
        #pragma unroll
        for (int bb = 0; bb < 4; ++bb) { acc[bb][0] = 0; acc[bb][1] = 0; }

        const u64* xrow = x2 + (size_t)((site & 1) * NB) * 65;

        for (int c = 0; c < CPS; ++c) {
            const int gh = site * CPS + c;

            // own group for chunk gh landed, then half-wide visibility
            asm volatile("cp.async.wait_group 1;\n" ::: "memory");
            half_bar(h);                     // chunk gh visible; buf (gh+2)%3 free
            issue_chunk(gh + 2, h, lid, smem_base, cores);

            if (c == 0) {
                // half A stages x for next site (other parity buffer)
                if (site + 1 < NSITES && tid < NB * 16) {
                    int br = tid >> 4, q = tid & 15;
                    float4 xv = x4[((size_t)(bbase + br) * NSITES + site + 1) * 16 + q];
                    u64* dstx = &x2[(size_t)(((site + 1) & 1) * NB + br) * 65 + 4 * q];
                    dstx[0] = pack2(xv.x, xv.x); dstx[1] = pack2(xv.y, xv.y);
                    dstx[2] = pack2(xv.z, xv.z); dstx[3] = pack2(xv.w, xv.w);
                }
                // pack res pairs (res_s ordered by prev site's full sync)
                #pragma unroll
                for (int bb = 0; bb < 4; ++bb)
                    #pragma unroll
                    for (int i = 0; i < 4; ++i) {
                        float v = res_s[(B0 + bb) * 33 + d0 + i];
                        rp[bb][i] = pack2(v, v);
                    }
            }

            // compute this chunk's 4 f-slices
            const float* cb = buff + (size_t)(h * 3 + (gh % 3)) * (CHUNK_B / 4)
                            + d0 * 128 + r0;
            #pragma unroll
            for (int fl = 0; fl < 4; ++fl) {
                ulonglong2 c0 = *(const ulonglong2*)(cb       + fl * 32);
                ulonglong2 c1 = *(const ulonglong2*)(cb + 128 + fl * 32);
                ulonglong2 c2 = *(const ulonglong2*)(cb + 256 + fl * 32);
                ulonglong2 c3 = *(const ulonglong2*)(cb + 384 + fl * 32);
                const int fg = h * 32 + c * 4 + fl;
                #pragma unroll
                for (int bb = 0; bb < 4; ++bb) {
                    u64 s0 = fma2(rp[bb][0], c0.x, zero);
                    u64 s1 = fma2(rp[bb][0], c0.y, zero);
                    s0 = fma2(rp[bb][1], c1.x, s0);
                    s1 = fma2(rp[bb][1], c1.y, s1);
                    s0 = fma2(rp[bb][2], c2.x, s0);
                    s1 = fma2(rp[bb][2], c2.y, s1);
                    s0 = fma2(rp[bb][3], c3.x, s0);
                    s1 = fma2(rp[bb][3], c3.y, s1);
                    u64 xv = xrow[(size_t)(B0 + bb) * 65 + fg];   // (x,x) pair
                    acc[bb][0] = fma2(xv, s0, acc[bb][0]);
                    acc[bb][1] = fma2(xv, s1, acc[bb][1]);
                }
            }
        }

        // write (half, dq) partials
        #pragma unroll
        for (int bb = 0; bb < 4; ++bb) {
            float* pb = part + (size_t)(slice * NB + B0 + bb) * 36;
            *(u64*)(pb + r0)     = acc[bb][0];
            *(u64*)(pb + r0 + 2) = acc[bb][1];
        }
        __syncthreads();                    // all partials visible (full CTA)

        // reduce 16 slices -> new res (512 slots, 1 per thread)
        {
            int b = tid >> 5, r = tid & 31;
            float v = 0.0f;
            #pragma unroll
            for (int k = 0; k < 16; ++k) v += part[(size_t)(k * NB + b) * 36 + r];
            res_s[b * 33 + r] = v;
        }
        __syncthreads();                    // res_s + x(next) visible to both halves
    }

    // val[b] = res[b] . end
    if (tid < NB) {
        float v = 0.0f;
        #pragma unroll
        for (int r = 0; r < DB; ++r) v += res_s[tid * 33 + r] * endv[r];
        val_s[tid] = v;
    }
    __syncthreads();

    // out[b][o] = val[b] * fc_w[o] + fc_b[o]   (512 threads, 8 batches each)
    {
        const int o  = tid & 255;
        const int jh = tid >> 8;
        const float w  = fc_w[o];
        const float bi = fc_b[o];
        #pragma unroll
        for (int j = 0; j < 8; ++j) {
            int b = jh * 8 + j;
            out[(size_t)(bbase + b) * OUTD + o] = val_s[b] * w + bi;
        }
    }
}

extern "C" void kernel_launch(void* const* d_in, const int* in_sizes, int n_in,
                              void* d_out, int out_size)
{
    (void)in_sizes; (void)n_in; (void)out_size;
    const float* x_p     = (const float*)d_in[0];
    const float* cores_p = (const float*)d_in[1];
    const float* start_p = (const float*)d_in[2];
    const float* end_p   = (const float*)d_in[3];
    const float* fcw_p   = (const float*)d_in[4];
    const float* fcb_p   = (const float*)d_in[5];
    float* out_p = (float*)d_out;

    cudaFuncSetAttribute(mps_encoder_kernel,
                         cudaFuncAttributeMaxDynamicSharedMemorySize, SMEM_TOTAL);

    mps_encoder_kernel<<<2048 / NB, THREADS, SMEM_TOTAL>>>(
        x_p, cores_p, start_p, end_p, fcw_p, fcb_p, out_p);
}

// round 12
// speedup vs baseline: 1.7197x; 1.7197x over previous
#include <cuda_runtime.h>
#include <cuda_bf16.h>
#include <cstdint>

// MPS memory encoder, Round 11: tensor-core (mma.sync bf16 3-pass) pipeline.
// (Resubmission of the R10 design — R11 bench was an infra failure with no
//  kernel signal; layouts re-audited against the PTX m16n8k16 fragment spec.)
//
//   m[b,d,r] = sum_f x[b,f]*core[d,f,r] is a per-site GEMM independent of the
//   chain. Split operands into bf16 hi/lo (v = hi + lo), compute
//   m = xh*ch + xl*ch + xh*cl in f32 accumulators (drop xl*cl ~ 2^-16).
//   Operands are pre-stored in exact m16n8k16 fragment order so the GEMM
//   kernel loads them with one LDG.128 per fragment record.
//
//   Main kernel: 128 CTAs x 512 threads, 16 batches/CTA (M=16).
//   Warp w owns n-cols [64w, 64w+64) (n = d*32+r  =>  d in {2w, 2w+1}).
//   Chain partial is lane-local from the D fragments; CTA reduce = 2 barriers.

#define NSITES  128
#define FEAT    64
#define DB      32
#define OUTD    256
#define NB      16

typedef unsigned u32;

// ---- static scratch (no allocations) ----
// core fragments: [site][kt4][ntg128][lane32] x uint4{bh0,bh1,bl0,bl1} = 33.5MB
__device__ uint4 g_cfrag[2097152];
// x fragments: [bblock128][site][kt4][hl2][lane32] x uint4{a0,a1,a2,a3} = 67MB
__device__ uint4 g_xfrag[4194304];

// ---- helpers ----
__device__ __forceinline__ u32 pack2bf(__nv_bfloat16 a, __nv_bfloat16 b) {
    __nv_bfloat162 p; p.x = a; p.y = b;
    return *(u32*)&p;
}
// split two floats -> (hi packed pair, lo packed pair)
__device__ __forceinline__ void split_pair(float v0, float v1, u32& hw, u32& lw) {
    __nv_bfloat16 h0 = __float2bfloat16_rn(v0);
    __nv_bfloat16 h1 = __float2bfloat16_rn(v1);
    hw = pack2bf(h0, h1);
    lw = pack2bf(__float2bfloat16_rn(v0 - __bfloat162float(h0)),
                 __float2bfloat16_rn(v1 - __bfloat162float(h1)));
}

#define MMA16816(c0,c1,c2,c3, a0,a1,a2,a3, b0,b1)                            \
    asm volatile("mma.sync.aligned.m16n8k16.row.col.f32.bf16.bf16.f32 "      \
        "{%0,%1,%2,%3}, {%4,%5,%6,%7}, {%8,%9}, {%0,%1,%2,%3};\n"            \
        : "+f"(c0), "+f"(c1), "+f"(c2), "+f"(c3)                             \
        : "r"(a0), "r"(a1), "r"(a2), "r"(a3), "r"(b0), "r"(b1))

// ---- Phase 0a: core -> B fragments (bf16 hi/lo) ----
// fragment (site,kt,ntg,lane): col n = ntg*8 + lane/4 (d=n>>5, r=n&31),
// rows k = kt*16 + (lane%4)*2 + {0,1}  (b0)  and +8,+9 (b1).
__global__ __launch_bounds__(256)
void cfrag_kernel(const float* __restrict__ cores)
{
    u32 g    = blockIdx.x * 256 + threadIdx.x;   // 2,097,152 total
    u32 lane = g & 31;
    u32 ntg  = (g >> 5) & 127;
    u32 kt   = (g >> 12) & 3;
    u32 site = g >> 14;

    u32 n = ntg * 8 + (lane >> 2);
    u32 d = n >> 5, r = n & 31;
    u32 f0 = kt * 16 + (lane & 3) * 2;
    const float* cb = cores + ((size_t)(site * 32 + d) * 64) * 32 + r;

    float v0 = cb[(f0    ) * 32];
    float v1 = cb[(f0 + 1) * 32];
    float v2 = cb[(f0 + 8) * 32];
    float v3 = cb[(f0 + 9) * 32];

    u32 bh0, bl0, bh1, bl1;
    split_pair(v0, v1, bh0, bl0);
    split_pair(v2, v3, bh1, bl1);
    g_cfrag[g] = make_uint4(bh0, bh1, bl0, bl1);
}

// ---- Phase 0b: x -> A fragments (bf16 hi/lo) ----
// fragment (bblock,site,kt,lane): rows m = lane/4 (+8),
// cols k = kt*16 + (lane%4)*2 + {0,1} (a0/a1) and +8,+9 (a2/a3).
__global__ __launch_bounds__(256)
void xfrag_kernel(const float* __restrict__ x)
{
    u32 g      = blockIdx.x * 256 + threadIdx.x;  // 2,097,152 total
    u32 lane   = g & 31;
    u32 kt     = (g >> 5) & 3;
    u32 site   = (g >> 7) & 127;
    u32 bblock = g >> 14;

    u32 m0 = lane >> 2;
    u32 k0 = kt * 16 + (lane & 3) * 2;
    const float* xr0 = x + ((size_t)(bblock * 16 + m0) * 128 + site) * 64 + k0;
    const float* xr1 = xr0 + (size_t)8 * 128 * 64;   // row m0+8

    u32 a0h, a0l, a1h, a1l, a2h, a2l, a3h, a3l;
    split_pair(xr0[0], xr0[1], a0h, a0l);
    split_pair(xr1[0], xr1[1], a1h, a1l);
    split_pair(xr0[8], xr0[9], a2h, a2l);
    split_pair(xr1[8], xr1[9], a3h, a3l);

    size_t base = ((((size_t)bblock * 128 + site) * 4 + kt) * 2) * 32 + lane;
    g_xfrag[base]      = make_uint4(a0h, a1h, a2h, a3h);   // hi
    g_xfrag[base + 32] = make_uint4(a0l, a1l, a2l, a3l);   // lo
}

// ---- Phase 1+2: per-site MMA + chain ----
__global__ __launch_bounds__(512, 1)
void mma_chain_kernel(const float* __restrict__ start,
                      const float* __restrict__ endv,
                      const float* __restrict__ fc_w,
                      const float* __restrict__ fc_b,
                      float* __restrict__ out)
{
    __shared__ float res_s[NB][33];
    __shared__ float part[16][NB][36];
    __shared__ float val_s[NB];

    const int tid  = threadIdx.x;
    const int w    = tid >> 5;
    const int lane = tid & 31;
    const int bblock = blockIdx.x;

    // init res = start
    {
        int b = tid >> 5, d = tid & 31;
        res_s[b][d] = start[d];
    }
    __syncthreads();

    const int b0 = lane >> 2;           // D-fragment row (batch within block)
    const int b1 = b0 + 8;
    const int c2 = (lane & 3) * 2;      // D-fragment col base within n8 tile

    for (int site = 0; site < NSITES; ++site) {
        float acc[8][4];
        #pragma unroll
        for (int nt = 0; nt < 8; ++nt)
            #pragma unroll
            for (int j = 0; j < 4; ++j) acc[nt][j] = 0.0f;

        const uint4* Ab = g_xfrag + ((((size_t)bblock * 128 + site) * 4) * 2) * 32 + lane;
        const uint4* Bb = g_cfrag + (((size_t)site * 4) * 128 + w * 8) * 32 + lane;

        #pragma unroll
        for (int kt = 0; kt < 4; ++kt) {
            uint4 ah = Ab[kt * 64];          // hi frags (stride 2*32 uint4 per kt)
            uint4 al = Ab[kt * 64 + 32];     // lo frags
            const uint4* Bk = Bb + (size_t)kt * 128 * 32;
            #pragma unroll
            for (int nt = 0; nt < 8; ++nt) {
                uint4 bb = Bk[nt * 32];      // {bh0,bh1,bl0,bl1}
                MMA16816(acc[nt][0], acc[nt][1], acc[nt][2], acc[nt][3],
                         ah.x, ah.y, ah.z, ah.w, bb.x, bb.y);   // xh*ch
                MMA16816(acc[nt][0], acc[nt][1], acc[nt][2], acc[nt][3],
                         al.x, al.y, al.z, al.w, bb.x, bb.y);   // xl*ch
                MMA16816(acc[nt][0], acc[nt][1], acc[nt][2], acc[nt][3],
                         ah.x, ah.y, ah.z, ah.w, bb.z, bb.w);   // xh*cl
            }
        }

        // chain partial: warp w covers d = 2w (nt 0..3) and 2w+1 (nt 4..7).
        // D rows = batches b0,b1; col r = nt*8 + c2 + {0,1}.
        float r00 = res_s[b0][2 * w],  r01 = res_s[b0][2 * w + 1];
        float r10 = res_s[b1][2 * w],  r11 = res_s[b1][2 * w + 1];
        #pragma unroll
        for (int nt = 0; nt < 4; ++nt) {
            int rr = nt * 8 + c2;
            float p00 = r00 * acc[nt][0] + r01 * acc[nt + 4][0];
            float p01 = r00 * acc[nt][1] + r01 * acc[nt + 4][1];
            float p10 = r10 * acc[nt][2] + r11 * acc[nt + 4][2];
            float p11 = r10 * acc[nt][3] + r11 * acc[nt + 4][3];
            *(float2*)&part[w][b0][rr] = make_float2(p00, p01);
            *(float2*)&part[w][b1][rr] = make_float2(p10, p11);
        }
        __syncthreads();

        // reduce 16 warps -> new res (512 slots, 1 per thread)
        {
            int b = tid >> 5, r = tid & 31;
            float v = 0.0f;
            #pragma unroll
            for (int k = 0; k < 16; ++k) v += part[k][b][r];
            res_s[b][r] = v;
        }
        __syncthreads();
    }

    // val[b] = res[b] . end
    if (tid < NB) {
        float v = 0.0f;
        #pragma unroll
        for (int r = 0; r < DB; ++r) v += res_s[tid][r] * endv[r];
        val_s[tid] = v;
    }
    __syncthreads();

    // out[b][o] = val[b]*fc_w[o] + fc_b[o]
    {
        const int o  = tid & 255;
        const int jh = tid >> 8;
        const float wv = fc_w[o];
        const float bi = fc_b[o];
        #pragma unroll
        for (int j = 0; j < 8; ++j) {
            int b = jh * 8 + j;
            out[(size_t)(bblock * NB + b) * OUTD + o] = val_s[b] * wv + bi;
        }
    }
}

extern "C" void kernel_launch(void* const* d_in, const int* in_sizes, int n_in,
                              void* d_out, int out_size)
{
    (void)in_sizes; (void)n_in; (void)out_size;
    const float* x_p     = (const float*)d_in[0];
    const float* cores_p = (const float*)d_in[1];
    const float* start_p = (const float*)d_in[2];
    const float* end_p   = (const float*)d_in[3];
    const float* fcw_p   = (const float*)d_in[4];
    const float* fcb_p   = (const float*)d_in[5];
    float* out_p = (float*)d_out;

    cfrag_kernel<<<8192, 256>>>(cores_p);
    xfrag_kernel<<<8192, 256>>>(x_p);
    mma_chain_kernel<<<128, 512>>>(start_p, end_p, fcw_p, fcb_p, out_p);
}

// round 14
// speedup vs baseline: 2.1353x; 1.2417x over previous
#include <cuda_runtime.h>
#include <cuda_bf16.h>
#include <cstdint>

// MPS memory encoder, Round 12: tensor-core bf16 2-pass pipeline.
//
//   m[b,d,r] = sum_f x[b,f]*core[d,f,r] per-site GEMM on HMMA.
//   x split into bf16 hi/lo (x = xh + xl); core quantized to bf16 (ch).
//   m = xh*ch + xl*ch  (dropped x*cl ~ 2^-9/product; measured chain
//   cancellation ~1e-3 from R12 => predicted final rel_err ~2e-6).
//   vs R11: B fragments are hi-only uint2 -> HALF the L2 traffic of the
//   main kernel (its binding constraint) and 2/3 the HMMA work.
//
//   Main kernel: 128 CTAs x 512 threads, 16 batches/CTA (M=16).
//   Warp w owns n-cols [64w, 64w+64) (n = d*32+r  =>  d in {2w, 2w+1}).
//   Chain partial is lane-local from the D fragments; 2 barriers/site.

#define NSITES  128
#define FEAT    64
#define DB      32
#define OUTD    256
#define NB      16

typedef unsigned u32;

// ---- static scratch (no allocations) ----
// core fragments (hi only): [site][kt4][ntg128][lane32] x uint2{bh0,bh1} = 16.8MB
__device__ uint2 g_cfrag[2097152];
// x fragments: [bblock128][site][kt4][hl2][lane32] x uint4{a0,a1,a2,a3} = 67MB
__device__ uint4 g_xfrag[4194304];

// ---- helpers ----
__device__ __forceinline__ u32 pack2bf(__nv_bfloat16 a, __nv_bfloat16 b) {
    __nv_bfloat162 p; p.x = a; p.y = b;
    return *(u32*)&p;
}
// split two floats -> (hi packed pair, lo packed pair)
__device__ __forceinline__ void split_pair(float v0, float v1, u32& hw, u32& lw) {
    __nv_bfloat16 h0 = __float2bfloat16_rn(v0);
    __nv_bfloat16 h1 = __float2bfloat16_rn(v1);
    hw = pack2bf(h0, h1);
    lw = pack2bf(__float2bfloat16_rn(v0 - __bfloat162float(h0)),
                 __float2bfloat16_rn(v1 - __bfloat162float(h1)));
}
// hi-only packed pair
__device__ __forceinline__ u32 hi_pair(float v0, float v1) {
    return pack2bf(__float2bfloat16_rn(v0), __float2bfloat16_rn(v1));
}

#define MMA16816(c0,c1,c2,c3, a0,a1,a2,a3, b0,b1)                            \
    asm volatile("mma.sync.aligned.m16n8k16.row.col.f32.bf16.bf16.f32 "      \
        "{%0,%1,%2,%3}, {%4,%5,%6,%7}, {%8,%9}, {%0,%1,%2,%3};\n"            \
        : "+f"(c0), "+f"(c1), "+f"(c2), "+f"(c3)                             \
        : "r"(a0), "r"(a1), "r"(a2), "r"(a3), "r"(b0), "r"(b1))

// ---- Phase 0a: core -> B fragments (bf16 hi only) ----
// fragment (site,kt,ntg,lane): col n = ntg*8 + lane/4 (d=n>>5, r=n&31),
// rows k = kt*16 + (lane%4)*2 + {0,1}  (b0)  and +8,+9 (b1).
__global__ __launch_bounds__(256)
void cfrag_kernel(const float* __restrict__ cores)
{
    u32 g    = blockIdx.x * 256 + threadIdx.x;   // 2,097,152 total
    u32 lane = g & 31;
    u32 ntg  = (g >> 5) & 127;
    u32 kt   = (g >> 12) & 3;
    u32 site = g >> 14;

    u32 n = ntg * 8 + (lane >> 2);
    u32 d = n >> 5, r = n & 31;
    u32 f0 = kt * 16 + (lane & 3) * 2;
    const float* cb = cores + ((size_t)(site * 32 + d) * 64) * 32 + r;

    float v0 = cb[(f0    ) * 32];
    float v1 = cb[(f0 + 1) * 32];
    float v2 = cb[(f0 + 8) * 32];
    float v3 = cb[(f0 + 9) * 32];

    g_cfrag[g] = make_uint2(hi_pair(v0, v1), hi_pair(v2, v3));
}

// ---- Phase 0b: x -> A fragments (bf16 hi/lo) ----
// fragment (bblock,site,kt,lane): rows m = lane/4 (+8),
// cols k = kt*16 + (lane%4)*2 + {0,1} (a0/a1) and +8,+9 (a2/a3).
__global__ __launch_bounds__(256)
void xfrag_kernel(const float* __restrict__ x)
{
    u32 g      = blockIdx.x * 256 + threadIdx.x;  // 2,097,152 total
    u32 lane   = g & 31;
    u32 kt     = (g >> 5) & 3;
    u32 site   = (g >> 7) & 127;
    u32 bblock = g >> 14;

    u32 m0 = lane >> 2;
    u32 k0 = kt * 16 + (lane & 3) * 2;
    const float* xr0 = x + ((size_t)(bblock * 16 + m0) * 128 + site) * 64 + k0;
    const float* xr1 = xr0 + (size_t)8 * 128 * 64;   // row m0+8

    u32 a0h, a0l, a1h, a1l, a2h, a2l, a3h, a3l;
    split_pair(xr0[0], xr0[1], a0h, a0l);
    split_pair(xr1[0], xr1[1], a1h, a1l);
    split_pair(xr0[8], xr0[9], a2h, a2l);
    split_pair(xr1[8], xr1[9], a3h, a3l);

    size_t base = ((((size_t)bblock * 128 + site) * 4 + kt) * 2) * 32 + lane;
    g_xfrag[base]      = make_uint4(a0h, a1h, a2h, a3h);   // hi
    g_xfrag[base + 32] = make_uint4(a0l, a1l, a2l, a3l);   // lo
}

// ---- Phase 1+2: per-site MMA + chain ----
__global__ __launch_bounds__(512, 1)
void mma_chain_kernel(const float* __restrict__ start,
                      const float* __restrict__ endv,
                      const float* __restrict__ fc_w,
                      const float* __restrict__ fc_b,
                      float* __restrict__ out)
{
    __shared__ float res_s[NB][33];
    __shared__ float part[16][NB][36];
    __shared__ float val_s[NB];

    const int tid  = threadIdx.x;
    const int w    = tid >> 5;
    const int lane = tid & 31;
    const int bblock = blockIdx.x;

    // init res = start
    {
        int b = tid >> 5, d = tid & 31;
        res_s[b][d] = start[d];
    }
    __syncthreads();

    const int b0 = lane >> 2;           // D-fragment row (batch within block)
    const int b1 = b0 + 8;
    const int c2 = (lane & 3) * 2;      // D-fragment col base within n8 tile

    for (int site = 0; site < NSITES; ++site) {
        float acc[8][4];
        #pragma unroll
        for (int nt = 0; nt < 8; ++nt)
            #pragma unroll
            for (int j = 0; j < 4; ++j) acc[nt][j] = 0.0f;

        const uint4* Ab = g_xfrag + ((((size_t)bblock * 128 + site) * 4) * 2) * 32 + lane;
        const uint2* Bb = g_cfrag + (((size_t)site * 4) * 128 + w * 8) * 32 + lane;

        #pragma unroll
        for (int kt = 0; kt < 4; ++kt) {
            uint4 ah = Ab[kt * 64];          // hi frags (stride 2*32 uint4 per kt)
            uint4 al = Ab[kt * 64 + 32];     // lo frags
            const uint2* Bk = Bb + (size_t)kt * 128 * 32;
            #pragma unroll
            for (int nt = 0; nt < 8; ++nt) {
                uint2 bb = Bk[nt * 32];      // {bh0,bh1}
                MMA16816(acc[nt][0], acc[nt][1], acc[nt][2], acc[nt][3],
                         ah.x, ah.y, ah.z, ah.w, bb.x, bb.y);   // xh*ch
                MMA16816(acc[nt][0], acc[nt][1], acc[nt][2], acc[nt][3],
                         al.x, al.y, al.z, al.w, bb.x, bb.y);   // xl*ch
            }
        }

        // chain partial: warp w covers d = 2w (nt 0..3) and 2w+1 (nt 4..7).
        // D rows = batches b0,b1; col r = nt*8 + c2 + {0,1}.
        float r00 = res_s[b0][2 * w],  r01 = res_s[b0][2 * w + 1];
        float r10 = res_s[b1][2 * w],  r11 = res_s[b1][2 * w + 1];
        #pragma unroll
        for (int nt = 0; nt < 4; ++nt) {
            int rr = nt * 8 + c2;
            float p00 = r00 * acc[nt][0] + r01 * acc[nt + 4][0];
            float p01 = r00 * acc[nt][1] + r01 * acc[nt + 4][1];
            float p10 = r10 * acc[nt][2] + r11 * acc[nt + 4][2];
            float p11 = r10 * acc[nt][3] + r11 * acc[nt + 4][3];
            *(float2*)&part[w][b0][rr] = make_float2(p00, p01);
            *(float2*)&part[w][b1][rr] = make_float2(p10, p11);
        }
        __syncthreads();

        // reduce 16 warps -> new res (512 slots, 1 per thread)
        {
            int b = tid >> 5, r = tid & 31;
            float v = 0.0f;
            #pragma unroll
            for (int k = 0; k < 16; ++k) v += part[k][b][r];
            res_s[b][r] = v;
        }
        __syncthreads();
    }

    // val[b] = res[b] . end
    if (tid < NB) {
        float v = 0.0f;
        #pragma unroll
        for (int r = 0; r < DB; ++r) v += res_s[tid][r] * endv[r];
        val_s[tid] = v;
    }
    __syncthreads();

    // out[b][o] = val[b]*fc_w[o] + fc_b[o]
    {
        const int o  = tid & 255;
        const int jh = tid >> 8;
        const float wv = fc_w[o];
        const float bi = fc_b[o];
        #pragma unroll
        for (int j = 0; j < 8; ++j) {
            int b = jh * 8 + j;
            out[(size_t)(bblock * NB + b) * OUTD + o] = val_s[b] * wv + bi;
        }
    }
}

extern "C" void kernel_launch(void* const* d_in, const int* in_sizes, int n_in,
                              void* d_out, int out_size)
{
    (void)in_sizes; (void)n_in; (void)out_size;
    const float* x_p     = (const float*)d_in[0];
    const float* cores_p = (const float*)d_in[1];
    const float* start_p = (const float*)d_in[2];
    const float* end_p   = (const float*)d_in[3];
    const float* fcw_p   = (const float*)d_in[4];
    const float* fcb_p   = (const float*)d_in[5];
    float* out_p = (float*)d_out;

    cfrag_kernel<<<8192, 256>>>(cores_p);
    xfrag_kernel<<<8192, 256>>>(x_p);
    mma_chain_kernel<<<128, 512>>>(start_p, end_p, fcw_p, fcb_p, out_p);
}

// round 15
// speedup vs baseline: 3.8419x; 1.7992x over previous
#include <cuda_runtime.h>
#include <cuda_bf16.h>
#include <cstdint>

// MPS memory encoder, Round 15: single-pass bf16 HMMA + depth-2 pipelining.
//
//   m[b,d,r] = sum_f x[b,f]*core[d,f,r] per-site GEMM on HMMA, single pass
//   (m ~ xh*ch). Dropped xl*ch and x*cl terms each measured to contribute
//   ~2.4e-7 final rel_err via chain cancellation -> predicted ~5e-7 total.
//   vs R12: half the HMMA work, half the xfrag traffic, and a depth-2
//   register pipeline so B/A fragment loads stay 2 stages ahead of their
//   consuming MMAs (in flight across the per-site reduce barriers).
//
//   Main kernel: 128 CTAs x 512 threads, 16 batches/CTA (M=16).
//   Warp w owns n-cols [64w, 64w+64) (n = d*32+r => d in {2w, 2w+1}).
//   Chain partial is lane-local from the D fragments; 2 barriers/site.

#define NSITES  128
#define FEAT    64
#define DB      32
#define OUTD    256
#define NB      16

typedef unsigned u32;

// ---- static scratch (no allocations) ----
// core fragments (hi only): [site][kt4][ntg128][lane32] x uint2{bh0,bh1} = 16.8MB
__device__ uint2 g_cfrag[2097152];
// x fragments (hi only): [bblock128][site][kt4][lane32] x uint4{a0..a3} = 33.5MB
__device__ uint4 g_xfrag[2097152];

// ---- helpers ----
__device__ __forceinline__ u32 pack2bf(__nv_bfloat16 a, __nv_bfloat16 b) {
    __nv_bfloat162 p; p.x = a; p.y = b;
    return *(u32*)&p;
}
__device__ __forceinline__ u32 hi_pair(float v0, float v1) {
    return pack2bf(__float2bfloat16_rn(v0), __float2bfloat16_rn(v1));
}

#define MMA16816(c0,c1,c2,c3, a0,a1,a2,a3, b0,b1)                            \
    asm volatile("mma.sync.aligned.m16n8k16.row.col.f32.bf16.bf16.f32 "      \
        "{%0,%1,%2,%3}, {%4,%5,%6,%7}, {%8,%9}, {%0,%1,%2,%3};\n"            \
        : "+f"(c0), "+f"(c1), "+f"(c2), "+f"(c3)                             \
        : "r"(a0), "r"(a1), "r"(a2), "r"(a3), "r"(b0), "r"(b1))

// ---- Phase 0a: core -> B fragments (bf16 hi only) ----
// fragment (site,kt,ntg,lane): col n = ntg*8 + lane/4 (d=n>>5, r=n&31),
// rows k = kt*16 + (lane%4)*2 + {0,1}  (b0)  and +8,+9 (b1).
__global__ __launch_bounds__(256)
void cfrag_kernel(const float* __restrict__ cores)
{
    u32 g    = blockIdx.x * 256 + threadIdx.x;   // 2,097,152 total
    u32 lane = g & 31;
    u32 ntg  = (g >> 5) & 127;
    u32 kt   = (g >> 12) & 3;
    u32 site = g >> 14;

    u32 n = ntg * 8 + (lane >> 2);
    u32 d = n >> 5, r = n & 31;
    u32 f0 = kt * 16 + (lane & 3) * 2;
    const float* cb = cores + ((size_t)(site * 32 + d) * 64) * 32 + r;

    float v0 = cb[(f0    ) * 32];
    float v1 = cb[(f0 + 1) * 32];
    float v2 = cb[(f0 + 8) * 32];
    float v3 = cb[(f0 + 9) * 32];

    g_cfrag[g] = make_uint2(hi_pair(v0, v1), hi_pair(v2, v3));
}

// ---- Phase 0b: x -> A fragments (bf16 hi only) ----
// fragment (bblock,site,kt,lane): rows m = lane/4 (+8),
// cols k = kt*16 + (lane%4)*2 + {0,1} (a0/a1) and +8,+9 (a2/a3).
__global__ __launch_bounds__(256)
void xfrag_kernel(const float* __restrict__ x)
{
    u32 g      = blockIdx.x * 256 + threadIdx.x;  // 2,097,152 total
    u32 lane   = g & 31;
    u32 kt     = (g >> 5) & 3;
    u32 site   = (g >> 7) & 127;
    u32 bblock = g >> 14;

    u32 m0 = lane >> 2;
    u32 k0 = kt * 16 + (lane & 3) * 2;
    const float* xr0 = x + ((size_t)(bblock * 16 + m0) * 128 + site) * 64 + k0;
    const float* xr1 = xr0 + (size_t)8 * 128 * 64;   // row m0+8

    g_xfrag[(((size_t)bblock * 128 + site) * 4 + kt) * 32 + lane] =
        make_uint4(hi_pair(xr0[0], xr0[1]), hi_pair(xr1[0], xr1[1]),
                   hi_pair(xr0[8], xr0[9]), hi_pair(xr1[8], xr1[9]));
}

// ---- Phase 1+2: per-site MMA + chain, depth-2 register pipeline ----
__global__ __launch_bounds__(512, 1)
void mma_chain_kernel(const float* __restrict__ start,
                      const float* __restrict__ endv,
                      const float* __restrict__ fc_w,
                      const float* __restrict__ fc_b,
                      float* __restrict__ out)
{
    __shared__ float res_s[NB][33];
    __shared__ float part[16][NB][36];
    __shared__ float val_s[NB];

    const int tid  = threadIdx.x;
    const int w    = tid >> 5;
    const int lane = tid & 31;
    const int bblock = blockIdx.x;

    // init res = start
    {
        int b = tid >> 5, d = tid & 31;
        res_s[b][d] = start[d];
    }
    __syncthreads();

    const int b0 = lane >> 2;           // D-fragment row (batch within block)
    const int b1 = b0 + 8;
    const int c2 = (lane & 3) * 2;      // D-fragment col base within n8 tile

    // fragment bases: index by global frag id fidx = site*4 + kt
    const uint2* Bbase = g_cfrag + (size_t)(w * 8) * 32 + lane;   // + fidx*4096 + nt*32
    const uint4* Abase = g_xfrag + (size_t)bblock * 512 * 32 + lane; // + fidx*32

    uint2 bb[2][8];
    uint4 aa[2];

    // prologue: load frag 0 -> buf0, frag 1 -> buf1
    #pragma unroll
    for (int i = 0; i < 8; ++i) bb[0][i] = Bbase[i * 32];
    aa[0] = Abase[0];
    #pragma unroll
    for (int i = 0; i < 8; ++i) bb[1][i] = Bbase[4096 + i * 32];
    aa[1] = Abase[32];

    for (int site = 0; site < NSITES; ++site) {
        float acc[8][4];
        #pragma unroll
        for (int nt = 0; nt < 8; ++nt)
            #pragma unroll
            for (int j = 0; j < 4; ++j) acc[nt][j] = 0.0f;

        #pragma unroll
        for (int kt = 0; kt < 4; ++kt) {
            const int buf = kt & 1;
            uint4 ah = aa[buf];
            #pragma unroll
            for (int nt = 0; nt < 8; ++nt) {
                MMA16816(acc[nt][0], acc[nt][1], acc[nt][2], acc[nt][3],
                         ah.x, ah.y, ah.z, ah.w, bb[buf][nt].x, bb[buf][nt].y);
            }
            // refill this buffer with fragment 2 ahead (crosses into site+1;
            // wraps to site 0 at the tail -- dummy loads, valid memory)
            int fidx = site * 4 + kt + 2;
            if (fidx >= NSITES * 4) fidx -= NSITES * 4;
            const uint2* Bp = Bbase + (size_t)fidx * 4096;
            #pragma unroll
            for (int i = 0; i < 8; ++i) bb[buf][i] = Bp[i * 32];
            aa[buf] = Abase[fidx * 32];
        }

        // chain partial: warp w covers d = 2w (nt 0..3) and 2w+1 (nt 4..7).
        // D rows = batches b0,b1; col r = nt*8 + c2 + {0,1}.
        float r00 = res_s[b0][2 * w],  r01 = res_s[b0][2 * w + 1];
        float r10 = res_s[b1][2 * w],  r11 = res_s[b1][2 * w + 1];
        #pragma unroll
        for (int nt = 0; nt < 4; ++nt) {
            int rr = nt * 8 + c2;
            float p00 = r00 * acc[nt][0] + r01 * acc[nt + 4][0];
            float p01 = r00 * acc[nt][1] + r01 * acc[nt + 4][1];
            float p10 = r10 * acc[nt][2] + r11 * acc[nt + 4][2];
            float p11 = r10 * acc[nt][3] + r11 * acc[nt + 4][3];
            *(float2*)&part[w][b0][rr] = make_float2(p00, p01);
            *(float2*)&part[w][b1][rr] = make_float2(p10, p11);
        }
        __syncthreads();

        // reduce 16 warps -> new res (512 slots, 1 per thread)
        {
            int b = tid >> 5, r = tid & 31;
            float v = 0.0f;
            #pragma unroll
            for (int k = 0; k < 16; ++k) v += part[k][b][r];
            res_s[b][r] = v;
        }
        __syncthreads();
    }

    // val[b] = res[b] . end
    if (tid < NB) {
        float v = 0.0f;
        #pragma unroll
        for (int r = 0; r < DB; ++r) v += res_s[tid][r] * endv[r];
        val_s[tid] = v;
    }
    __syncthreads();

    // out[b][o] = val[b]*fc_w[o] + fc_b[o]
    {
        const int o  = tid & 255;
        const int jh = tid >> 8;
        const float wv = fc_w[o];
        const float bi = fc_b[o];
        #pragma unroll
        for (int j = 0; j < 8; ++j) {
            int b = jh * 8 + j;
            out[(size_t)(bblock * NB + b) * OUTD + o] = val_s[b] * wv + bi;
        }
    }
}

extern "C" void kernel_launch(void* const* d_in, const int* in_sizes, int n_in,
                              void* d_out, int out_size)
{
    (void)in_sizes; (void)n_in; (void)out_size;
    const float* x_p     = (const float*)d_in[0];
    const float* cores_p = (const float*)d_in[1];
    const float* start_p = (const float*)d_in[2];
    const float* end_p   = (const float*)d_in[3];
    const float* fcw_p   = (const float*)d_in[4];
    const float* fcb_p   = (const float*)d_in[5];
    float* out_p = (float*)d_out;

    cfrag_kernel<<<8192, 256>>>(cores_p);
    xfrag_kernel<<<8192, 256>>>(x_p);
    mma_chain_kernel<<<128, 512>>>(start_p, end_p, fcw_p, fcb_p, out_p);
}

// round 16
// speedup vs baseline: 4.7952x; 1.2481x over previous
#include <cuda_runtime.h>
#include <cuda_bf16.h>
#include <cuda_fp8.h>
#include <cstdint>

// MPS memory encoder, Round 16: e4m3 HMMA (m16n8k32) + single-barrier chain.
//
//   m[b,d,r] = sum_f x[b,f]*core[d,f,r] per-site GEMM on fp8 tensor cores.
//   x, core quantized to e4m3 with fixed power-of-2 scales (S_X=16, S_C=1024);
//   dequant 1/(S_X*S_C) folded into the chain res values (exact, no error).
//   Calibrated error model (R12/R14/R15): final rel_err ~ 2e-4 * per-product
//   RMS eps; e4m3 eps ~ 0.026 -> predicted ~1e-5 (threshold 1e-3).
//
//   Chain uses per-warp self-reduce of double-buffered partials (pad 38 ->
//   conflict-free LDS) + 4 shuffles -> ONE __syncthreads per site.
//
//   Main kernel: 128 CTAs x 512 threads, 16 batches/CTA (M=16).
//   Warp w owns n-cols [64w, 64w+64) (n = d*32+r => d in {2w,2w+1}).

#define NSITES  128
#define FEAT    64
#define DB      32
#define OUTD    256
#define NB      16

#define S_C   1024.0f
#define S_X   16.0f
#define INVS  (1.0f / (1024.0f * 16.0f))

typedef unsigned u32;

// ---- static scratch (no allocations) ----
// core fp8 fragments: [site][kt2][ntg128][lane32] x uint2{b0,b1} = 8.4MB
__device__ uint2 g_cfrag[1048576];
// x fp8 fragments: [bblock128][site][kt2][lane32] x uint4{a0..a3} = 16.8MB
__device__ uint4 g_xfrag[1048576];

// smem layout (dynamic): part[2][16][16][38] f32 | res_s[16][33] | val_s[16]
#define PART_WORDS  (2 * 16 * 16 * 38)         // 19456 words = 77824 B
#define RES_OFF_W   PART_WORDS
#define VAL_OFF_W   (PART_WORDS + 16 * 33)
#define SMEM_TOTAL  ((PART_WORDS + 16 * 33 + 16) * 4)

// ---- helpers ----
__device__ __forceinline__ u32 pack4fp8(float f0, float f1, float f2, float f3) {
    u32 r =  (u32)__nv_cvt_float_to_fp8(f0, __NV_SATFINITE, __NV_E4M3);
    r |= (u32)__nv_cvt_float_to_fp8(f1, __NV_SATFINITE, __NV_E4M3) << 8;
    r |= (u32)__nv_cvt_float_to_fp8(f2, __NV_SATFINITE, __NV_E4M3) << 16;
    r |= (u32)__nv_cvt_float_to_fp8(f3, __NV_SATFINITE, __NV_E4M3) << 24;
    return r;
}

#define MMAFP8(c0,c1,c2,c3, a0,a1,a2,a3, b0,b1)                              \
    asm volatile("mma.sync.aligned.m16n8k32.row.col.f32.e4m3.e4m3.f32 "      \
        "{%0,%1,%2,%3}, {%4,%5,%6,%7}, {%8,%9}, {%0,%1,%2,%3};\n"            \
        : "+f"(c0), "+f"(c1), "+f"(c2), "+f"(c3)                             \
        : "r"(a0), "r"(a1), "r"(a2), "r"(a3), "r"(b0), "r"(b1))

// ---- Phase 0a: core -> fp8 B fragments ----
// frag (site,kt,ntg,lane): n = ntg*8 + lane/4 (d=n>>5, r=n&31),
// k rows = kt*32 + (lane%4)*4 + {0..3} (b0) and +16 (b1); k maps to f.
__global__ __launch_bounds__(256)
void cfrag_kernel(const float* __restrict__ cores)
{
    u32 g    = blockIdx.x * 256 + threadIdx.x;   // 1,048,576 total
    u32 lane = g & 31;
    u32 ntg  = (g >> 5) & 127;
    u32 kt   = (g >> 12) & 1;
    u32 site = g >> 13;

    u32 n = ntg * 8 + (lane >> 2);
    u32 d = n >> 5, r = n & 31;
    u32 f0 = kt * 32 + (lane & 3) * 4;
    const float* cb = cores + ((size_t)(site * 32 + d) * 64) * 32 + r;

    u32 b0 = pack4fp8(cb[(f0     ) * 32] * S_C, cb[(f0 +  1) * 32] * S_C,
                      cb[(f0 +  2) * 32] * S_C, cb[(f0 +  3) * 32] * S_C);
    u32 b1 = pack4fp8(cb[(f0 + 16) * 32] * S_C, cb[(f0 + 17) * 32] * S_C,
                      cb[(f0 + 18) * 32] * S_C, cb[(f0 + 19) * 32] * S_C);
    g_cfrag[g] = make_uint2(b0, b1);
}

// ---- Phase 0b: x -> fp8 A fragments ----
// frag (bblock,site,kt,lane): rows m = lane/4 (+8),
// k cols = kt*32 + (lane%4)*4 + {0..3} (a0/a1) and +16 (a2/a3).
__global__ __launch_bounds__(256)
void xfrag_kernel(const float* __restrict__ x)
{
    u32 g      = blockIdx.x * 256 + threadIdx.x;  // 1,048,576 total
    u32 lane   = g & 31;
    u32 kt     = (g >> 5) & 1;
    u32 site   = (g >> 6) & 127;
    u32 bblock = g >> 13;

    u32 m0 = lane >> 2;
    u32 k0 = kt * 32 + (lane & 3) * 4;
    const float4* xr0 = (const float4*)
        (x + ((size_t)(bblock * 16 + m0) * 128 + site) * 64 + k0);
    const float4* xr1 = (const float4*)((const float*)xr0 + (size_t)8 * 128 * 64);

    float4 v0 = xr0[0], v1 = xr1[0], v2 = xr0[4], v3 = xr1[4];  // +16 f = 4 float4
    g_xfrag[(((size_t)bblock * 128 + site) * 2 + kt) * 32 + lane] = make_uint4(
        pack4fp8(v0.x * S_X, v0.y * S_X, v0.z * S_X, v0.w * S_X),
        pack4fp8(v1.x * S_X, v1.y * S_X, v1.z * S_X, v1.w * S_X),
        pack4fp8(v2.x * S_X, v2.y * S_X, v2.z * S_X, v2.w * S_X),
        pack4fp8(v3.x * S_X, v3.y * S_X, v3.z * S_X, v3.w * S_X));
}

// ---- Phase 1+2: per-site fp8 MMA + single-barrier chain ----
__global__ __launch_bounds__(512, 1)
void mma_chain_kernel(const float* __restrict__ start,
                      const float* __restrict__ endv,
                      const float* __restrict__ fc_w,
                      const float* __restrict__ fc_b,
                      float* __restrict__ out)
{
    extern __shared__ float sm[];
    float* part  = sm;                    // [2][16][16][38]
    float* res_s = sm + RES_OFF_W;        // [16][33]
    float* val_s = sm + VAL_OFF_W;        // [16]

    const int tid  = threadIdx.x;
    const int w    = tid >> 5;
    const int lane = tid & 31;
    const int bblock = blockIdx.x;

    const int b0 = lane >> 2;             // D-frag row (batch in block)
    const int b1 = b0 + 8;
    const int c2 = (lane & 3) * 2;        // D-frag col base in n8 tile

    // self-reduce lane mapping: lane holds res[rb_][rr_]
    const int rb_ = lane >> 1;
    const int rr_ = 2 * w + (lane & 1);
    const float* rred = part + (size_t)rb_ * 38 + rr_;   // + pb*9728 + k*608

    // fragment bases, fidx = site*2 + kt (256 total)
    const uint2* Bbase = g_cfrag + (size_t)(w * 8) * 32 + lane;     // + fidx*4096 + nt*32
    const uint4* Abase = g_xfrag + (size_t)bblock * 256 * 32 + lane; // + fidx*32

    uint2 bb[2][8];
    uint4 aa[2];
    #pragma unroll
    for (int i = 0; i < 8; ++i) bb[0][i] = Bbase[i * 32];
    aa[0] = Abase[0];
    #pragma unroll
    for (int i = 0; i < 8; ++i) bb[1][i] = Bbase[4096 + i * 32];
    aa[1] = Abase[32];

    for (int site = 0; site < NSITES; ++site) {
        float acc[8][4];
        #pragma unroll
        for (int nt = 0; nt < 8; ++nt)
            #pragma unroll
            for (int j = 0; j < 4; ++j) acc[nt][j] = 0.0f;

        #pragma unroll
        for (int kt = 0; kt < 2; ++kt) {
            uint4 ah = aa[kt];
            #pragma unroll
            for (int nt = 0; nt < 8; ++nt)
                MMAFP8(acc[nt][0], acc[nt][1], acc[nt][2], acc[nt][3],
                       ah.x, ah.y, ah.z, ah.w, bb[kt][nt].x, bb[kt][nt].y);
            // refill 2 fragments ahead (wraps to site 0: dummy, valid memory)
            int fidx = site * 2 + kt + 2;
            if (fidx >= NSITES * 2) fidx -= NSITES * 2;
            const uint2* Bp = Bbase + (size_t)fidx * 4096;
            #pragma unroll
            for (int i = 0; i < 8; ++i) bb[kt][i] = Bp[i * 32];
            aa[kt] = Abase[fidx * 32];
        }

        // chain: res for this site (self-reduce of prev partials), *INVS dequant
        float rs;
        if (site == 0) {
            rs = start[rr_] * INVS;
        } else {
            const float* pp = rred + (size_t)((site & 1) ^ 1) * 9728;
            float v = 0.0f;
            #pragma unroll
            for (int k = 0; k < 16; ++k) v += pp[k * 608];
            rs = v * INVS;
        }
        float r00 = __shfl_sync(0xFFFFFFFFu, rs, b0 * 2);
        float r01 = __shfl_sync(0xFFFFFFFFu, rs, b0 * 2 + 1);
        float r10 = __shfl_sync(0xFFFFFFFFu, rs, b0 * 2 + 16);
        float r11 = __shfl_sync(0xFFFFFFFFu, rs, b0 * 2 + 17);

        // write partials (warp w: d=2w -> nt 0..3, d=2w+1 -> nt 4..7)
        float* pw = part + (size_t)((site & 1) * 16 + w) * 608;
        #pragma unroll
        for (int nt = 0; nt < 4; ++nt) {
            int rr = nt * 8 + c2;
            *(float2*)(pw + (size_t)b0 * 38 + rr) = make_float2(
                r00 * acc[nt][0] + r01 * acc[nt + 4][0],
                r00 * acc[nt][1] + r01 * acc[nt + 4][1]);
            *(float2*)(pw + (size_t)b1 * 38 + rr) = make_float2(
                r10 * acc[nt][2] + r11 * acc[nt + 4][2],
                r10 * acc[nt][3] + r11 * acc[nt + 4][3]);
        }
        __syncthreads();   // ONE barrier per site
    }

    // final res: self-reduce of site-127 partials (buffer 1)
    {
        const float* pp = rred + 9728;
        float v = 0.0f;
        #pragma unroll
        for (int k = 0; k < 16; ++k) v += pp[k * 608];
        res_s[rb_ * 33 + rr_] = v * INVS;
    }
    __syncthreads();

    // val[b] = res[b] . end
    if (tid < NB) {
        float v = 0.0f;
        #pragma unroll
        for (int r = 0; r < DB; ++r) v += res_s[tid * 33 + r] * endv[r];
        val_s[tid] = v;
    }
    __syncthreads();

    // out[b][o] = val[b]*fc_w[o] + fc_b[o]
    {
        const int o  = tid & 255;
        const int jh = tid >> 8;
        const float wv = fc_w[o];
        const float bi = fc_b[o];
        #pragma unroll
        for (int j = 0; j < 8; ++j) {
            int b = jh * 8 + j;
            out[(size_t)(bblock * NB + b) * OUTD + o] = val_s[b] * wv + bi;
        }
    }
}

extern "C" void kernel_launch(void* const* d_in, const int* in_sizes, int n_in,
                              void* d_out, int out_size)
{
    (void)in_sizes; (void)n_in; (void)out_size;
    const float* x_p     = (const float*)d_in[0];
    const float* cores_p = (const float*)d_in[1];
    const float* start_p = (const float*)d_in[2];
    const float* end_p   = (const float*)d_in[3];
    const float* fcw_p   = (const float*)d_in[4];
    const float* fcb_p   = (const float*)d_in[5];
    float* out_p = (float*)d_out;

    cudaFuncSetAttribute(mma_chain_kernel,
                         cudaFuncAttributeMaxDynamicSharedMemorySize, SMEM_TOTAL);

    cfrag_kernel<<<4096, 256>>>(cores_p);
    xfrag_kernel<<<4096, 256>>>(x_p);
    mma_chain_kernel<<<128, 512, SMEM_TOTAL>>>(start_p, end_p, fcw_p, fcb_p, out_p);
}